// round 1
// baseline (speedup 1.0000x reference)
#include <cuda_runtime.h>
#include <math.h>

// Problem dims (fixed by the dataset)
#define BB 2
#define DD 64
#define HH 128
#define WW 128
#define HW (HH*WW)
#define SP (DD*HW)     // 1,048,576 per batch
#define NT (BB*SP)     // 2,097,152 total voxels

// ---------------- scratch fields (__device__ globals: allocation-free) ------
__device__ float g_prob[NT];
__device__ float g_yt[NT];
__device__ float g_hard[NT];
__device__ float g_skelP[NT];   // soft_skel(prob)
__device__ float g_skelT[NT];   // soft_skel(y_true)
__device__ float g_skelH[NT];   // soft_skel(hard)
__device__ float g_accL[NT];    // EDT acc for y_true
__device__ float g_accP[NT];    // EDT acc for hard
__device__ float g_tA[NT];
__device__ float g_tB[NT];

// sums: 0 p1, 1 y, 2 p1*y, 3 ce, 4 conn, 5 dir,
//       6 skelP*y, 7 skelP, 8 skelT*p, 9 skelT,
//       10 inter1, 11 union1, 12 inter2, 13 union2
__device__ double g_sum[14];
__device__ unsigned g_rmx[4];   // [0,1]=label b0,b1  [2,3]=pred b0,b1
__device__ unsigned g_rmn[4];

// ---------------- reduction helpers (256-thread blocks) ---------------------
__device__ __forceinline__ int flat_tid() { return threadIdx.y * blockDim.x + threadIdx.x; }

__device__ __forceinline__ void block_add(double v, double* dst) {
    int tid = flat_tid();
    for (int o = 16; o; o >>= 1) v += __shfl_down_sync(0xffffffffu, v, o);
    __shared__ double sh[8];
    int lane = tid & 31, wid = tid >> 5;
    if (lane == 0) sh[wid] = v;
    __syncthreads();
    if (wid == 0) {
        double x = (lane < 8) ? sh[lane] : 0.0;
        for (int o = 4; o; o >>= 1) x += __shfl_down_sync(0xffffffffu, x, o);
        if (lane == 0) atomicAdd(dst, x);
    }
    __syncthreads();
}

__device__ __forceinline__ float block_maxv(float v) {
    int tid = flat_tid();
    for (int o = 16; o; o >>= 1) v = fmaxf(v, __shfl_down_sync(0xffffffffu, v, o));
    __shared__ float sh[8];
    int lane = tid & 31, wid = tid >> 5;
    if (lane == 0) sh[wid] = v;
    __syncthreads();
    float r = v;
    if (wid == 0) {
        float x = (lane < 8) ? sh[lane] : -1e30f;
        for (int o = 4; o; o >>= 1) x = fmaxf(x, __shfl_down_sync(0xffffffffu, x, o));
        r = x;
    }
    __syncthreads();
    return r;
}

__device__ __forceinline__ float block_minv(float v) {
    int tid = flat_tid();
    for (int o = 16; o; o >>= 1) v = fminf(v, __shfl_down_sync(0xffffffffu, v, o));
    __shared__ float sh[8];
    int lane = tid & 31, wid = tid >> 5;
    if (lane == 0) sh[wid] = v;
    __syncthreads();
    float r = v;
    if (wid == 0) {
        float x = (lane < 8) ? sh[lane] : 1e30f;
        for (int o = 4; o; o >>= 1) x = fminf(x, __shfl_down_sync(0xffffffffu, x, o));
        r = x;
    }
    __syncthreads();
    return r;
}

// ---------------- kernels ----------------------------------------------------
__global__ void k_zero() {
    int t = threadIdx.x;
    if (t < 14) g_sum[t] = 0.0;
    if (t < 4) { g_rmx[t] = 0u; g_rmn[t] = 0x7f800000u; }
}

// softmax prob, y_true, hard + dice/ce/connectivity sums
__global__ void k_init(const float* __restrict__ net, const int* __restrict__ tgt) {
    int i = blockIdx.x * blockDim.x + threadIdx.x;
    float p1 = 0.f, yv = 0.f, p1y = 0.f, ce = 0.f, conn = 0.f;
    if (i < NT) {
        int b = i / SP, s = i - b * SP;
        float x0 = net[(size_t)(b * 2) * SP + s];
        float x1 = net[(size_t)(b * 2 + 1) * SP + s];
        int t = tgt[i];
        float m = fmaxf(x0, x1);
        float e0 = expf(x0 - m), e1 = expf(x1 - m);
        float z = e0 + e1;
        p1 = e1 / z;
        yv = (t > 0) ? 1.f : 0.f;
        g_prob[i] = p1;
        g_yt[i]   = yv;
        g_hard[i] = (p1 > 0.5f) ? 1.f : 0.f;
        p1y = p1 * yv;
        float lse = m + logf(z);
        ce = -(((t > 0) ? x1 : x0) - lse);
        conn = fabsf(((x0 > 0.5f) ? 1.f : 0.f) - yv) + fabsf(((x1 > 0.5f) ? 1.f : 0.f) - yv);
    }
    block_add((double)p1,  &g_sum[0]);
    block_add((double)yv,  &g_sum[1]);
    block_add((double)p1y, &g_sum[2]);
    block_add((double)ce,  &g_sum[3]);
    block_add((double)conn,&g_sum[4]);
}

// directional (Sobel cosine) term
__global__ void k_sobel(const float* __restrict__ net, const int* __restrict__ tgt) {
    int w = blockIdx.x * blockDim.x + threadIdx.x;
    int h = blockIdx.y * blockDim.y + threadIdx.y;
    int z = blockIdx.z;
    int b = z / DD, d = z - b * DD;
    const float smw[3] = {1.f, 2.f, 1.f};
    const float grw[3] = {-1.f, 0.f, 1.f};
    float gx = 0.f, gy = 0.f, gz = 0.f, tx = 0.f, ty = 0.f, tz = 0.f;
    const float* p0 = net + (size_t)(b * 2) * SP;
    const int*   tb = tgt + (size_t)b * SP;
    #pragma unroll
    for (int dd = -1; dd <= 1; dd++) {
        int dn = d + dd; if (dn < 0 || dn >= DD) continue;
        #pragma unroll
        for (int hh = -1; hh <= 1; hh++) {
            int hn = h + hh; if (hn < 0 || hn >= HH) continue;
            #pragma unroll
            for (int ww = -1; ww <= 1; ww++) {
                int wn = w + ww; if (wn < 0 || wn >= WW) continue;
                int o = dn * HW + hn * WW + wn;
                float v  = p0[o];
                float tv = (float)tb[o];
                float ca = smw[hh + 1] * grw[ww + 1];   // kx: grad w, smooth h
                float cb = smw[dd + 1] * grw[ww + 1];   // ky: grad w, smooth d
                float cc = smw[dd + 1] * grw[hh + 1];   // kz: grad h, smooth d
                gx += v * ca;  gy += v * cb;  gz += v * cc;
                tx += tv * ca; ty += tv * cb; tz += tv * cc;
            }
        }
    }
    float npn = sqrtf(gx * gx + gy * gy + gz * gz);
    float ia = 1.f / fmaxf(npn, 1e-12f);
    float px = gx * ia, py = gy * ia, pz = gz * ia;
    float ntn = sqrtf(tx * tx + ty * ty + tz * tz);
    float ib = 1.f / fmaxf(ntn, 1e-12f);
    float qx = tx * ib, qy = ty * ib, qz = tz * ib;
    float num = px * qx + py * qy + pz * qz;
    float den = fmaxf(sqrtf(px * px + py * py + pz * pz) *
                      sqrtf(qx * qx + qy * qy + qz * qz), 1e-8f);
    block_add((double)(num / den), &g_sum[5]);
}

// soft_erode: min over 7-point cross (OOB ignored)
__global__ void k_erode(const float* __restrict__ src, float* __restrict__ dst) {
    int w = blockIdx.x * blockDim.x + threadIdx.x;
    int h = blockIdx.y * blockDim.y + threadIdx.y;
    int z = blockIdx.z;
    int d = z % DD;
    int idx = z * HW + h * WW + w;
    float m = src[idx];
    if (d > 0)      m = fminf(m, src[idx - HW]);
    if (d < DD - 1) m = fminf(m, src[idx + HW]);
    if (h > 0)      m = fminf(m, src[idx - WW]);
    if (h < HH - 1) m = fminf(m, src[idx + WW]);
    if (w > 0)      m = fminf(m, src[idx - 1]);
    if (w < WW - 1) m = fminf(m, src[idx + 1]);
    dst[idx] = m;
}

// dilate27(nxt) fused with skel update:
//   delta = relu(cur - dilate(nxt));  first: skel = delta
//   else: skel += relu(delta - skel*delta)
__global__ void k_dilup(const float* __restrict__ nxt, const float* __restrict__ cur,
                        float* __restrict__ skel, int first) {
    int w = blockIdx.x * blockDim.x + threadIdx.x;
    int h = blockIdx.y * blockDim.y + threadIdx.y;
    int z = blockIdx.z;
    int d = z % DD;
    int idx = z * HW + h * WW + w;
    int d0 = (d > 0) ? -1 : 0, d1 = (d < DD - 1) ? 1 : 0;
    int h0 = (h > 0) ? -1 : 0, h1 = (h < HH - 1) ? 1 : 0;
    int w0 = (w > 0) ? -1 : 0, w1 = (w < WW - 1) ? 1 : 0;
    float m = nxt[idx];
    for (int dd = d0; dd <= d1; dd++)
        for (int hh = h0; hh <= h1; hh++)
            for (int ww = w0; ww <= w1; ww++)
                m = fmaxf(m, nxt[idx + dd * HW + hh * WW + ww]);
    float delta = fmaxf(cur[idx] - m, 0.f);
    if (first) {
        skel[idx] = delta;
    } else {
        float s = skel[idx];
        skel[idx] = s + fmaxf(delta - s * delta, 0.f);
    }
}

__global__ void k_edtinit(const float* __restrict__ mask, float* __restrict__ cur,
                          float* __restrict__ acc) {
    int i = blockIdx.x * blockDim.x + threadIdx.x;
    if (i < NT) { float v = mask[i]; cur[i] = v; acc[i] = v; }
}

// minpool27 fused with acc accumulation
__global__ void k_minacc(const float* __restrict__ src, float* __restrict__ dst,
                         float* __restrict__ acc) {
    int w = blockIdx.x * blockDim.x + threadIdx.x;
    int h = blockIdx.y * blockDim.y + threadIdx.y;
    int z = blockIdx.z;
    int d = z % DD;
    int idx = z * HW + h * WW + w;
    int d0 = (d > 0) ? -1 : 0, d1 = (d < DD - 1) ? 1 : 0;
    int h0 = (h > 0) ? -1 : 0, h1 = (h < HH - 1) ? 1 : 0;
    int w0 = (w > 0) ? -1 : 0, w1 = (w < WW - 1) ? 1 : 0;
    float m = src[idx];
    for (int dd = d0; dd <= d1; dd++)
        for (int hh = h0; hh <= h1; hh++)
            for (int ww = w0; ww <= w1; ww++)
                m = fminf(m, src[idx + dd * HW + hh * WW + ww]);
    dst[idx] = m;
    acc[idx] += m;
}

// per-batch rmax/rmin of skel radii (label + pred sides)
__global__ void k_radius() {
    int i = blockIdx.x * 256 + threadIdx.x;
    int b = i / SP;   // 256 | SP, so whole block shares b
    float radl = g_accL[i] * g_yt[i] * g_skelT[i];
    float spp  = g_skelH[i] * g_prob[i];
    float sb   = (spp > 0.5f) ? 1.f : 0.f;
    float radp = g_accP[i] * g_hard[i] * sb;
    float mxl = block_maxv(radl);
    float mnl = block_minv(radl);
    float mxp = block_maxv(radp);
    float mnp = block_minv(radp);
    if (flat_tid() == 0) {
        atomicMax(&g_rmx[b],     __float_as_uint(mxl));
        atomicMin(&g_rmn[b],     __float_as_uint(mnl));
        atomicMax(&g_rmx[2 + b], __float_as_uint(mxp));
        atomicMin(&g_rmn[2 + b], __float_as_uint(mnp));
    }
}

// clDice sums + both general_union sums
__global__ void k_final() {
    int i = blockIdx.x * 256 + threadIdx.x;
    int b = i / SP;
    float spv = g_skelP[i];
    float st  = g_skelT[i];
    float y   = g_yt[i];
    float p   = g_prob[i];
    float hd  = g_hard[i];
    float sh  = g_skelH[i];

    float rmaxl = fmaxf(__uint_as_float(g_rmx[b]), 1.f);
    float rminl = fmaxf(__uint_as_float(g_rmn[b]), 1.f);
    float rmaxp = fmaxf(__uint_as_float(g_rmx[2 + b]), 1.f);
    float rminp = fmaxf(__uint_as_float(g_rmn[2 + b]), 1.f);

    // label side weights
    float distl = g_accL[i] * y;
    float qvl = fminf(distl, rmaxl) / rmaxl * y;
    float radl = distl * st;
    float il = (rmaxl - radl + rminl) / rmaxl; il *= il;
    float qsl = il * st * st;

    // pred side weights
    float spp = sh * p;
    float sb  = (spp > 0.5f) ? 1.f : 0.f;
    float distp = g_accP[i] * hd;
    float qvp = fminf(distp, rmaxp) / rmaxp * p;
    float radp = distp * sb;
    float ip = (rmaxp - radp + rminp) / rmaxp; ip *= ip;
    float qsp = ip * sb * spp;

    float inter1 = qsp * powf(qsp + 1e-4f, 0.7f) * qvl;
    float union1 = qsp * (0.1f * qsp + 0.9f * qvl);
    float inter2 = qsl * powf(qvp + 1e-4f, 0.7f) * qsl;
    float union2 = qsl * (0.1f * qvp + 0.9f * qsl);

    block_add((double)(spv * y), &g_sum[6]);
    block_add((double)spv,       &g_sum[7]);
    block_add((double)(st * p),  &g_sum[8]);
    block_add((double)st,        &g_sum[9]);
    block_add((double)inter1,    &g_sum[10]);
    block_add((double)union1,    &g_sum[11]);
    block_add((double)inter2,    &g_sum[12]);
    block_add((double)union2,    &g_sum[13]);
}

__global__ void k_combine(float* out) {
    double tp = g_sum[2];
    double fp = g_sum[0] - tp;
    double fn = g_sum[1] - tp;
    double dice = -((2.0 * tp + 1e-5) / (2.0 * tp + fp + fn + 1e-5));
    double ce   = g_sum[3] / (double)NT;
    double tprec = (g_sum[6] + 1.0) / (g_sum[7] + 1.0);
    double tsens = (g_sum[8] + 1.0) / (g_sum[9] + 1.0);
    double cl = 1.0 - 2.0 * tprec * tsens / (tprec + tsens);
    double dir  = 1.0 - g_sum[5] / (double)NT;
    double conn = g_sum[4] / (2.0 * (double)NT);
    double u1 = 1.0 - (g_sum[10] + 1.0) / (g_sum[11] + 1.0);
    double u2 = 1.0 - (g_sum[12] + 1.0) / (g_sum[13] + 1.0);
    out[0] = (float)(dice + ce + cl + dir + conn + u1 + u2);
}

// ---------------- host orchestration ----------------------------------------
static void run_soft_skel(const float* img, float* skel, float* A, float* B) {
    dim3 blk(32, 8, 1), grd(WW / 32, HH / 8, BB * DD);
    k_erode<<<grd, blk>>>(img, A);
    k_dilup<<<grd, blk>>>(A, img, skel, 1);
    float* cur = A; float* oth = B;
    for (int it = 0; it < 10; it++) {
        k_erode<<<grd, blk>>>(cur, oth);
        k_dilup<<<grd, blk>>>(oth, cur, skel, 0);
        float* t = cur; cur = oth; oth = t;
    }
}

static void run_edt(const float* mask, float* acc, float* A, float* B) {
    dim3 blk(32, 8, 1), grd(WW / 32, HH / 8, BB * DD);
    k_edtinit<<<NT / 256, 256>>>(mask, A, acc);
    float* cur = A; float* oth = B;
    for (int k = 0; k < 15; k++) {   // acc = sum of cur_0..cur_15
        k_minacc<<<grd, blk>>>(cur, oth, acc);
        float* t = cur; cur = oth; oth = t;
    }
}

extern "C" void kernel_launch(void* const* d_in, const int* in_sizes, int n_in,
                              void* d_out, int out_size) {
    (void)in_sizes; (void)n_in; (void)out_size;
    const float* net = (const float*)d_in[0];
    const int*   tgt = (const int*)d_in[1];
    float* out = (float*)d_out;

    float *prob, *yt, *hard, *skelP, *skelT, *skelH, *accL, *accP, *tA, *tB;
    cudaGetSymbolAddress((void**)&prob,  g_prob);
    cudaGetSymbolAddress((void**)&yt,    g_yt);
    cudaGetSymbolAddress((void**)&hard,  g_hard);
    cudaGetSymbolAddress((void**)&skelP, g_skelP);
    cudaGetSymbolAddress((void**)&skelT, g_skelT);
    cudaGetSymbolAddress((void**)&skelH, g_skelH);
    cudaGetSymbolAddress((void**)&accL,  g_accL);
    cudaGetSymbolAddress((void**)&accP,  g_accP);
    cudaGetSymbolAddress((void**)&tA,    g_tA);
    cudaGetSymbolAddress((void**)&tB,    g_tB);

    dim3 blk(32, 8, 1), grd(WW / 32, HH / 8, BB * DD);

    k_zero<<<1, 32>>>();
    k_init<<<NT / 256, 256>>>(net, tgt);
    k_sobel<<<grd, blk>>>(net, tgt);

    run_soft_skel(prob, skelP, tA, tB);   // skel of prob (continuous)
    run_soft_skel(yt,   skelT, tA, tB);   // skel of y_true
    run_soft_skel(hard, skelH, tA, tB);   // skel of hard prediction

    run_edt(yt,   accL, tA, tB);
    run_edt(hard, accP, tA, tB);

    k_radius<<<NT / 256, 256>>>();
    k_final<<<NT / 256, 256>>>();
    k_combine<<<1, 1>>>(out);
}

// round 2
// speedup vs baseline: 4.1298x; 4.1298x over previous
#include <cuda_runtime.h>
#include <math.h>

// Problem dims (fixed by the dataset)
#define BB 2
#define DD 64
#define HH 128
#define WW 128
#define HW (HH*WW)
#define SP (DD*HW)     // 1,048,576 per batch
#define NT (BB*SP)     // 2,097,152 total voxels

#define TH 8           // H rows per block
#define CHUNK 8        // D planes per block sweep
#define INFF __int_as_float(0x7f800000)

// ---------------- scratch fields (__device__ globals: allocation-free) ------
__device__ __align__(16) float g_P[NT];        // prob
__device__ __align__(16) float g_Y[NT];        // y_true
__device__ __align__(16) float g_H[NT];        // hard
__device__ __align__(16) float g_S[3*NT];      // skel outputs: P, T(y), H
__device__ __align__(16) float g_A[3*NT];      // skel chain ping
__device__ __align__(16) float g_B[3*NT];      // skel chain pong
__device__ __align__(16) float g_EA[2*NT];     // edt ping (Y, H)
__device__ __align__(16) float g_EB[2*NT];     // edt pong
__device__ __align__(16) float g_ACC[2*NT];    // edt acc (L, P)

// sums: 0 p1, 1 y, 2 p1*y, 3 ce, 4 conn, 5 dir,
//       6 skelP*y, 7 skelP, 8 skelT*p, 9 skelT,
//       10 inter1, 11 union1, 12 inter2, 13 union2
__device__ double g_sum[14];
__device__ unsigned g_rmx[4];   // [0,1]=label b0,b1  [2,3]=pred b0,b1
__device__ unsigned g_rmn[4];

// ---------------- small helpers ---------------------------------------------
template<bool MIN>
__device__ __forceinline__ float opf(float a, float b) { return MIN ? fminf(a, b) : fmaxf(a, b); }

template<bool MIN>
__device__ __forceinline__ float4 op4(float4 a, float4 b) {
    float4 o;
    o.x = opf<MIN>(a.x, b.x); o.y = opf<MIN>(a.y, b.y);
    o.z = opf<MIN>(a.z, b.z); o.w = opf<MIN>(a.w, b.w);
    return o;
}

template<bool MIN>
__device__ __forceinline__ float4 ident4() {
    float v = MIN ? INFF : -INFF;
    return make_float4(v, v, v, v);
}

// 1-D pool over W inside one warp (each lane owns 4 consecutive w)
template<bool MIN>
__device__ __forceinline__ float4 wpool(float4 v, int lane) {
    float idv = MIN ? INFF : -INFF;
    float l = __shfl_up_sync(0xffffffffu, v.w, 1);
    float r = __shfl_down_sync(0xffffffffu, v.x, 1);
    if (lane == 0) l = idv;
    if (lane == 31) r = idv;
    float4 o;
    o.x = opf<MIN>(opf<MIN>(l, v.x), v.y);
    o.y = opf<MIN>(opf<MIN>(v.x, v.y), v.z);
    o.z = opf<MIN>(opf<MIN>(v.y, v.z), v.w);
    o.w = opf<MIN>(opf<MIN>(v.z, v.w), r);
    return o;
}

// compute W+H pooled plane value for this thread's (row, lanes) at depth d
template<bool MIN>
__device__ __forceinline__ float4 plane_wh(const float* __restrict__ src, int h0, int d,
                                           int lane, int ty, float4* sm, int buf) {
    float4 id4 = ident4<MIN>();
    float4* S = sm + buf * ((TH + 2) * 32);
    if (d >= 0 && d < DD) {
        const float4* p = (const float4*)(src + (size_t)d * HW);
        float4 v = p[(h0 + ty) * 32 + lane];
        S[(ty + 1) * 32 + lane] = wpool<MIN>(v, lane);
        if (ty == 0)
            S[lane] = (h0 - 1 >= 0) ? wpool<MIN>(p[(h0 - 1) * 32 + lane], lane) : id4;
        if (ty == TH - 1)
            S[(TH + 1) * 32 + lane] = (h0 + TH < HH) ? wpool<MIN>(p[(h0 + TH) * 32 + lane], lane) : id4;
    }
    __syncthreads();
    if (d < 0 || d >= DD) return id4;
    float4 a = S[ty * 32 + lane];
    float4 b = S[(ty + 1) * 32 + lane];
    float4 c = S[(ty + 2) * 32 + lane];
    return op4<MIN>(op4<MIN>(a, b), c);
}

// erode-cross plane: returns original v plus min(wpool, hpool) for this plane
__device__ __forceinline__ void plane_cross(const float* __restrict__ src, int h0, int d,
                                            int lane, int ty, float4* sm, int buf,
                                            float4& v_out, float4& wh_out) {
    float4 id4 = ident4<true>();
    float4* S = sm + buf * ((TH + 2) * 32);
    float4 v = id4;
    if (d >= 0 && d < DD) {
        const float4* p = (const float4*)(src + (size_t)d * HW);
        v = p[(h0 + ty) * 32 + lane];
        S[(ty + 1) * 32 + lane] = v;                         // original for H pool
        if (ty == 0)
            S[lane] = (h0 - 1 >= 0) ? p[(h0 - 1) * 32 + lane] : id4;
        if (ty == TH - 1)
            S[(TH + 1) * 32 + lane] = (h0 + TH < HH) ? p[(h0 + TH) * 32 + lane] : id4;
    }
    __syncthreads();
    if (d < 0 || d >= DD) { v_out = id4; wh_out = id4; return; }
    float4 hm = op4<true>(op4<true>(S[ty * 32 + lane], S[(ty + 1) * 32 + lane]),
                          S[(TH + 2) * 32 - 32 + (ty - (TH - 1)) * 32 + lane]); // placeholder avoided below
    // recompute cleanly (compiler folds): hm = min of rows ty, ty+1, ty+2
    hm = op4<true>(op4<true>(S[ty * 32 + lane], S[(ty + 1) * 32 + lane]), S[(ty + 2) * 32 + lane]);
    float4 wm = wpool<true>(v, lane);
    v_out = v;
    wh_out = op4<true>(wm, hm);
}

__device__ __forceinline__ void zdecode(int z, int& f, int& b) { f = z >> 1; b = z & 1; }

// ---------------- sweep kernels ----------------------------------------------
// 27-point min pool fused with EDT accumulation (batched over grid.z fields)
__global__ void __launch_bounds__(256) k_minacc(const float* __restrict__ src_base,
                                                float* __restrict__ dst_base,
                                                float* __restrict__ acc_base) {
    __shared__ float4 sm[2 * (TH + 2) * 32];
    int lane = threadIdx.x, ty = threadIdx.y;
    int h0 = blockIdx.x * TH;
    int dz = blockIdx.y * CHUNK;
    int f, b; zdecode(blockIdx.z, f, b);
    size_t off = (size_t)f * NT + (size_t)b * SP;
    const float* src = src_base + off;
    float* dst = dst_base + off;
    float* acc = acc_base + off;

    int buf = 0;
    float4 pa = plane_wh<true>(src, h0, dz - 1, lane, ty, sm, buf); buf ^= 1;
    float4 pb = plane_wh<true>(src, h0, dz,     lane, ty, sm, buf); buf ^= 1;
    for (int d = dz; d < dz + CHUNK; d++) {
        float4 pc = plane_wh<true>(src, h0, d + 1, lane, ty, sm, buf); buf ^= 1;
        float4 o = op4<true>(op4<true>(pa, pb), pc);
        size_t ro = (size_t)d * (HW / 4) + (h0 + ty) * 32 + lane;
        ((float4*)dst)[ro] = o;
        float4 av = ((float4*)acc)[ro];
        av.x += o.x; av.y += o.y; av.z += o.z; av.w += o.w;
        ((float4*)acc)[ro] = av;
        pa = pb; pb = pc;
    }
}

// soft_erode: min over 7-point cross (batched 3 fields)
__global__ void __launch_bounds__(256) k_erode(const float* __restrict__ src_base,
                                               float* __restrict__ dst_base) {
    __shared__ float4 sm[2 * (TH + 2) * 32];
    int lane = threadIdx.x, ty = threadIdx.y;
    int h0 = blockIdx.x * TH;
    int dz = blockIdx.y * CHUNK;
    int f, b; zdecode(blockIdx.z, f, b);
    size_t off = (size_t)f * NT + (size_t)b * SP;
    const float* src = src_base + off;
    float* dst = dst_base + off;

    int buf = 0;
    float4 va, wa, vb, wb, vc, wc;
    plane_cross(src, h0, dz - 1, lane, ty, sm, buf, va, wa); buf ^= 1;
    plane_cross(src, h0, dz,     lane, ty, sm, buf, vb, wb); buf ^= 1;
    for (int d = dz; d < dz + CHUNK; d++) {
        plane_cross(src, h0, d + 1, lane, ty, sm, buf, vc, wc); buf ^= 1;
        float4 o = op4<true>(wb, op4<true>(va, vc));
        ((float4*)dst)[(size_t)d * (HW / 4) + (h0 + ty) * 32 + lane] = o;
        va = vb; wa = wb; vb = vc; wb = wc;
    }
}

// dilate27(nxt) fused with skel update (batched 3 fields)
__global__ void __launch_bounds__(256) k_dilup(const float* __restrict__ nxt_base,
                                               const float* __restrict__ cur_base,
                                               float* __restrict__ skel_base, int first) {
    __shared__ float4 sm[2 * (TH + 2) * 32];
    int lane = threadIdx.x, ty = threadIdx.y;
    int h0 = blockIdx.x * TH;
    int dz = blockIdx.y * CHUNK;
    int f, b; zdecode(blockIdx.z, f, b);
    size_t off = (size_t)f * NT + (size_t)b * SP;
    const float* nxt = nxt_base + off;
    const float* cur = cur_base + off;
    float* skel = skel_base + off;

    int buf = 0;
    float4 pa = plane_wh<false>(nxt, h0, dz - 1, lane, ty, sm, buf); buf ^= 1;
    float4 pb = plane_wh<false>(nxt, h0, dz,     lane, ty, sm, buf); buf ^= 1;
    for (int d = dz; d < dz + CHUNK; d++) {
        float4 pc = plane_wh<false>(nxt, h0, d + 1, lane, ty, sm, buf); buf ^= 1;
        float4 m = op4<false>(op4<false>(pa, pb), pc);
        size_t ro = (size_t)d * (HW / 4) + (h0 + ty) * 32 + lane;
        float4 cv = ((const float4*)cur)[ro];
        float4 dl;
        dl.x = fmaxf(cv.x - m.x, 0.f); dl.y = fmaxf(cv.y - m.y, 0.f);
        dl.z = fmaxf(cv.z - m.z, 0.f); dl.w = fmaxf(cv.w - m.w, 0.f);
        if (first) {
            ((float4*)skel)[ro] = dl;
        } else {
            float4 s = ((float4*)skel)[ro];
            s.x += fmaxf(dl.x - s.x * dl.x, 0.f);
            s.y += fmaxf(dl.y - s.y * dl.y, 0.f);
            s.z += fmaxf(dl.z - s.z * dl.z, 0.f);
            s.w += fmaxf(dl.w - s.w * dl.w, 0.f);
            ((float4*)skel)[ro] = s;
        }
        pa = pb; pb = pc;
    }
}

// ---------------- reduction helpers (256-thread blocks) ---------------------
__device__ __forceinline__ int flat_tid() { return threadIdx.y * blockDim.x + threadIdx.x; }

__device__ __forceinline__ void block_add(double v, double* dst) {
    int tid = flat_tid();
    for (int o = 16; o; o >>= 1) v += __shfl_down_sync(0xffffffffu, v, o);
    __shared__ double sh[8];
    int lane = tid & 31, wid = tid >> 5;
    if (lane == 0) sh[wid] = v;
    __syncthreads();
    if (wid == 0) {
        double x = (lane < 8) ? sh[lane] : 0.0;
        for (int o = 4; o; o >>= 1) x += __shfl_down_sync(0xffffffffu, x, o);
        if (lane == 0) atomicAdd(dst, x);
    }
    __syncthreads();
}

__device__ __forceinline__ float block_maxv(float v) {
    int tid = flat_tid();
    for (int o = 16; o; o >>= 1) v = fmaxf(v, __shfl_down_sync(0xffffffffu, v, o));
    __shared__ float sh[8];
    int lane = tid & 31, wid = tid >> 5;
    if (lane == 0) sh[wid] = v;
    __syncthreads();
    float r = v;
    if (wid == 0) {
        float x = (lane < 8) ? sh[lane] : -1e30f;
        for (int o = 4; o; o >>= 1) x = fmaxf(x, __shfl_down_sync(0xffffffffu, x, o));
        r = x;
    }
    __syncthreads();
    return r;
}

__device__ __forceinline__ float block_minv(float v) {
    int tid = flat_tid();
    for (int o = 16; o; o >>= 1) v = fminf(v, __shfl_down_sync(0xffffffffu, v, o));
    __shared__ float sh[8];
    int lane = tid & 31, wid = tid >> 5;
    if (lane == 0) sh[wid] = v;
    __syncthreads();
    float r = v;
    if (wid == 0) {
        float x = (lane < 8) ? sh[lane] : 1e30f;
        for (int o = 4; o; o >>= 1) x = fminf(x, __shfl_down_sync(0xffffffffu, x, o));
        r = x;
    }
    __syncthreads();
    return r;
}

// ---------------- pointwise / reduction kernels -------------------------------
__global__ void k_zero() {
    int t = threadIdx.x;
    if (t < 14) g_sum[t] = 0.0;
    if (t < 4) { g_rmx[t] = 0u; g_rmn[t] = 0x7f800000u; }
}

// softmax prob, y_true, hard + dice/ce/connectivity sums + skel-chain seeds
__global__ void k_init(const float* __restrict__ net, const int* __restrict__ tgt) {
    int i = blockIdx.x * blockDim.x + threadIdx.x;
    int b = i / SP, s = i - b * SP;
    float x0 = net[(size_t)(b * 2) * SP + s];
    float x1 = net[(size_t)(b * 2 + 1) * SP + s];
    int t = tgt[i];
    float m = fmaxf(x0, x1);
    float e0 = expf(x0 - m), e1 = expf(x1 - m);
    float z = e0 + e1;
    float p1 = e1 / z;
    float yv = (t > 0) ? 1.f : 0.f;
    float hd = (p1 > 0.5f) ? 1.f : 0.f;
    g_P[i] = p1; g_Y[i] = yv; g_H[i] = hd;
    g_A[i] = p1; g_A[NT + i] = yv; g_A[2 * NT + i] = hd;
    float lse = m + logf(z);
    float ce = -(((t > 0) ? x1 : x0) - lse);
    float conn = fabsf(((x0 > 0.5f) ? 1.f : 0.f) - yv) + fabsf(((x1 > 0.5f) ? 1.f : 0.f) - yv);
    block_add((double)p1,        &g_sum[0]);
    block_add((double)yv,        &g_sum[1]);
    block_add((double)(p1 * yv), &g_sum[2]);
    block_add((double)ce,        &g_sum[3]);
    block_add((double)conn,      &g_sum[4]);
}

__global__ void k_edtinit() {
    int i = blockIdx.x * blockDim.x + threadIdx.x;  // i in [0, 2*NT)
    float v = (i < NT) ? g_Y[i] : g_H[i - NT];
    g_EA[i] = v;
    g_ACC[i] = v;
}

// directional (Sobel cosine) term
__global__ void k_sobel(const float* __restrict__ net, const int* __restrict__ tgt) {
    int w = blockIdx.x * blockDim.x + threadIdx.x;
    int h = blockIdx.y * blockDim.y + threadIdx.y;
    int z = blockIdx.z;
    int b = z / DD, d = z - b * DD;
    const float smw[3] = {1.f, 2.f, 1.f};
    const float grw[3] = {-1.f, 0.f, 1.f};
    float gx = 0.f, gy = 0.f, gz = 0.f, tx = 0.f, ty = 0.f, tz = 0.f;
    const float* p0 = net + (size_t)(b * 2) * SP;
    const int*   tb = tgt + (size_t)b * SP;
    #pragma unroll
    for (int dd = -1; dd <= 1; dd++) {
        int dn = d + dd; if (dn < 0 || dn >= DD) continue;
        #pragma unroll
        for (int hh = -1; hh <= 1; hh++) {
            int hn = h + hh; if (hn < 0 || hn >= HH) continue;
            #pragma unroll
            for (int ww = -1; ww <= 1; ww++) {
                int wn = w + ww; if (wn < 0 || wn >= WW) continue;
                int o = dn * HW + hn * WW + wn;
                float v  = p0[o];
                float tv = (float)tb[o];
                float ca = smw[hh + 1] * grw[ww + 1];
                float cb = smw[dd + 1] * grw[ww + 1];
                float cc = smw[dd + 1] * grw[hh + 1];
                gx += v * ca;  gy += v * cb;  gz += v * cc;
                tx += tv * ca; ty += tv * cb; tz += tv * cc;
            }
        }
    }
    float npn = sqrtf(gx * gx + gy * gy + gz * gz);
    float ia = 1.f / fmaxf(npn, 1e-12f);
    float px = gx * ia, py = gy * ia, pz = gz * ia;
    float ntn = sqrtf(tx * tx + ty * ty + tz * tz);
    float ib = 1.f / fmaxf(ntn, 1e-12f);
    float qx = tx * ib, qy = ty * ib, qz = tz * ib;
    float num = px * qx + py * qy + pz * qz;
    float den = fmaxf(sqrtf(px * px + py * py + pz * pz) *
                      sqrtf(qx * qx + qy * qy + qz * qz), 1e-8f);
    block_add((double)(num / den), &g_sum[5]);
}

// per-batch rmax/rmin of skel radii (label + pred sides)
__global__ void k_radius() {
    int i = blockIdx.x * 256 + threadIdx.x;
    int b = i / SP;
    float radl = g_ACC[i] * g_Y[i] * g_S[NT + i];
    float spp  = g_S[2 * NT + i] * g_P[i];
    float sb   = (spp > 0.5f) ? 1.f : 0.f;
    float radp = g_ACC[NT + i] * g_H[i] * sb;
    float mxl = block_maxv(radl);
    float mnl = block_minv(radl);
    float mxp = block_maxv(radp);
    float mnp = block_minv(radp);
    if (flat_tid() == 0) {
        atomicMax(&g_rmx[b],     __float_as_uint(mxl));
        atomicMin(&g_rmn[b],     __float_as_uint(mnl));
        atomicMax(&g_rmx[2 + b], __float_as_uint(mxp));
        atomicMin(&g_rmn[2 + b], __float_as_uint(mnp));
    }
}

// clDice sums + both general_union sums
__global__ void k_final() {
    int i = blockIdx.x * 256 + threadIdx.x;
    int b = i / SP;
    float spv = g_S[i];
    float st  = g_S[NT + i];
    float y   = g_Y[i];
    float p   = g_P[i];
    float hd  = g_H[i];
    float sh  = g_S[2 * NT + i];

    float rmaxl = fmaxf(__uint_as_float(g_rmx[b]), 1.f);
    float rminl = fmaxf(__uint_as_float(g_rmn[b]), 1.f);
    float rmaxp = fmaxf(__uint_as_float(g_rmx[2 + b]), 1.f);
    float rminp = fmaxf(__uint_as_float(g_rmn[2 + b]), 1.f);

    float distl = g_ACC[i] * y;
    float qvl = fminf(distl, rmaxl) / rmaxl * y;
    float radl = distl * st;
    float il = (rmaxl - radl + rminl) / rmaxl; il *= il;
    float qsl = il * st * st;

    float spp = sh * p;
    float sb  = (spp > 0.5f) ? 1.f : 0.f;
    float distp = g_ACC[NT + i] * hd;
    float qvp = fminf(distp, rmaxp) / rmaxp * p;
    float radp = distp * sb;
    float ip = (rmaxp - radp + rminp) / rmaxp; ip *= ip;
    float qsp = ip * sb * spp;

    float inter1 = qsp * powf(qsp + 1e-4f, 0.7f) * qvl;
    float union1 = qsp * (0.1f * qsp + 0.9f * qvl);
    float inter2 = qsl * powf(qvp + 1e-4f, 0.7f) * qsl;
    float union2 = qsl * (0.1f * qvp + 0.9f * qsl);

    block_add((double)(spv * y), &g_sum[6]);
    block_add((double)spv,       &g_sum[7]);
    block_add((double)(st * p),  &g_sum[8]);
    block_add((double)st,        &g_sum[9]);
    block_add((double)inter1,    &g_sum[10]);
    block_add((double)union1,    &g_sum[11]);
    block_add((double)inter2,    &g_sum[12]);
    block_add((double)union2,    &g_sum[13]);
}

__global__ void k_combine(float* out) {
    double tp = g_sum[2];
    double fp = g_sum[0] - tp;
    double fn = g_sum[1] - tp;
    double dice = -((2.0 * tp + 1e-5) / (2.0 * tp + fp + fn + 1e-5));
    double ce   = g_sum[3] / (double)NT;
    double tprec = (g_sum[6] + 1.0) / (g_sum[7] + 1.0);
    double tsens = (g_sum[8] + 1.0) / (g_sum[9] + 1.0);
    double cl = 1.0 - 2.0 * tprec * tsens / (tprec + tsens);
    double dir  = 1.0 - g_sum[5] / (double)NT;
    double conn = g_sum[4] / (2.0 * (double)NT);
    double u1 = 1.0 - (g_sum[10] + 1.0) / (g_sum[11] + 1.0);
    double u2 = 1.0 - (g_sum[12] + 1.0) / (g_sum[13] + 1.0);
    out[0] = (float)(dice + ce + cl + dir + conn + u1 + u2);
}

// ---------------- host orchestration ----------------------------------------
extern "C" void kernel_launch(void* const* d_in, const int* in_sizes, int n_in,
                              void* d_out, int out_size) {
    (void)in_sizes; (void)n_in; (void)out_size;
    const float* net = (const float*)d_in[0];
    const int*   tgt = (const int*)d_in[1];
    float* out = (float*)d_out;

    float *A, *Bp, *S, *EA, *EB, *ACC;
    cudaGetSymbolAddress((void**)&A,   g_A);
    cudaGetSymbolAddress((void**)&Bp,  g_B);
    cudaGetSymbolAddress((void**)&S,   g_S);
    cudaGetSymbolAddress((void**)&EA,  g_EA);
    cudaGetSymbolAddress((void**)&EB,  g_EB);
    cudaGetSymbolAddress((void**)&ACC, g_ACC);

    dim3 blk(32, TH, 1);
    dim3 grd3(HH / TH, DD / CHUNK, 3 * BB);   // skel: 3 fields x batch
    dim3 grd2(HH / TH, DD / CHUNK, 2 * BB);   // edt: 2 fields x batch
    dim3 sblk(32, 8, 1), sgrd(WW / 32, HH / 8, BB * DD);

    k_zero<<<1, 32>>>();
    k_init<<<NT / 256, 256>>>(net, tgt);
    k_sobel<<<sgrd, sblk>>>(net, tgt);

    // three soft_skels, batched (fields: prob, y_true, hard), 11 erodes each
    k_erode<<<grd3, blk>>>(A, Bp);
    k_dilup<<<grd3, blk>>>(Bp, A, S, 1);
    float* cur = Bp; float* oth = A;
    for (int it = 0; it < 10; it++) {
        k_erode<<<grd3, blk>>>(cur, oth);
        k_dilup<<<grd3, blk>>>(oth, cur, S, 0);
        float* t = cur; cur = oth; oth = t;
    }

    // two EDT scans, batched (fields: y_true, hard)
    k_edtinit<<<2 * NT / 256, 256>>>();
    float* ec = EA; float* eo = EB;
    for (int k = 0; k < 15; k++) {
        k_minacc<<<grd2, blk>>>(ec, eo, ACC);
        float* t = ec; ec = eo; eo = t;
    }

    k_radius<<<NT / 256, 256>>>();
    k_final<<<NT / 256, 256>>>();
    k_combine<<<1, 1>>>(out);
}